// round 12
// baseline (speedup 1.0000x reference)
#include <cuda_runtime.h>
#include <cuda_fp16.h>
#include <stdint.h>
#include <math.h>

// ---------------- problem constants ----------------
#define N_TOK 32768      // B*T = 4*8192
#define C_DIM 1024
#define HS    2048
#define HR    1024
#define NE    8

// Token permutation: physical row = (t & 7) * 4096 + (t >> 3)  (residue-major).

// ---------------- GEMM tile config: 128x256 CTA tile, 64x64 warp tiles ----------
#define BM 128
#define BN 256
#define BK 64
#define NSTG 3
#define ASTR (BK + 8)    // 72 halfs/row (144B; banks 4r..4r+3 per row, conflict-free)
#define BSTR (BN + 8)    // 264 halfs/row (528B; 132w mod 32 = 4 -> conflict-free trans)
#define A_ST (BM * ASTR)             // 9216 halfs
#define B_ST (BK * BSTR)             // 16896 halfs
#define SMEM_BYTES (NSTG * (A_ST + B_ST) * 2)   // 156672 B, 1 CTA/SM

// ---------------- static scratch ----------------
__device__ __half g_xh[N_TOK * C_DIM];          // x fp16, residue-major permuted
__device__ __half g_sw1h[C_DIM * HS];
__device__ __half g_sw3h[C_DIM * HS];
__device__ __half g_sw2h[HS * C_DIM];           // pre-scaled by 0.5
__device__ __half g_w1h[NE * C_DIM * HR];
__device__ __half g_w2h[NE * HR * C_DIM];       // pre-scaled by 0.25
__device__ __half g_H2[N_TOK * HS];             // swiglu hidden, permuted rows
__device__ __half g_Hr[2 * N_TOK * HR];         // routed hidden [k*8+r][4096][HR]

// ---------------- small PTX helpers ----------------
__device__ __forceinline__ void cp16(void* s, const void* g) {
    unsigned sa = (unsigned)__cvta_generic_to_shared(s);
    asm volatile("cp.async.cg.shared.global [%0], [%1], 16;" :: "r"(sa), "l"(g));
}
__device__ __forceinline__ void ldsm4(uint32_t* r, const __half* p) {
    unsigned a = (unsigned)__cvta_generic_to_shared(p);
    asm volatile("ldmatrix.sync.aligned.m8n8.x4.shared.b16 {%0,%1,%2,%3}, [%4];"
                 : "=r"(r[0]), "=r"(r[1]), "=r"(r[2]), "=r"(r[3]) : "r"(a));
}
__device__ __forceinline__ void ldsm4t(uint32_t* r, const __half* p) {
    unsigned a = (unsigned)__cvta_generic_to_shared(p);
    asm volatile("ldmatrix.sync.aligned.m8n8.x4.trans.shared.b16 {%0,%1,%2,%3}, [%4];"
                 : "=r"(r[0]), "=r"(r[1]), "=r"(r[2]), "=r"(r[3]) : "r"(a));
}
__device__ __forceinline__ void mma16816(float* d, const uint32_t* a, const uint32_t* b) {
    asm volatile(
        "mma.sync.aligned.m16n8k16.row.col.f32.f16.f16.f32 "
        "{%0,%1,%2,%3},{%4,%5,%6,%7},{%8,%9},{%0,%1,%2,%3};"
        : "+f"(d[0]), "+f"(d[1]), "+f"(d[2]), "+f"(d[3])
        : "r"(a[0]), "r"(a[1]), "r"(a[2]), "r"(a[3]), "r"(b[0]), "r"(b[1]));
}

// ---------------- conversion kernels ----------------
__global__ void k_convx(const float* __restrict__ src, int n4) {
    int i = blockIdx.x * blockDim.x + threadIdx.x;
    if (i >= n4) return;
    int t = i >> 8;                 // token (256 float4 per row)
    int c = i & 255;
    int pr = ((t & 7) << 12) | (t >> 3);   // permuted row
    float4 v = ((const float4*)src)[i];
    __half2* d = (__half2*)g_xh + (size_t)pr * (C_DIM / 2) + c * 2;
    d[0] = __floats2half2_rn(v.x, v.y);
    d[1] = __floats2half2_rn(v.z, v.w);
}
__device__ __forceinline__ __half* conv_dst(int tag) {
    switch (tag) {
        case 3: return g_sw2h;
        case 4: return g_w1h;
        default: return g_w2h;
    }
}
__global__ void k_convert(const float* __restrict__ src, int tag, int n4, float scale) {
    int i = blockIdx.x * blockDim.x + threadIdx.x;
    if (i >= n4) return;
    float4 v = ((const float4*)src)[i];
    __half2* d = (__half2*)conv_dst(tag);
    d[2 * i]     = __floats2half2_rn(v.x * scale, v.y * scale);
    d[2 * i + 1] = __floats2half2_rn(v.z * scale, v.w * scale);
}
__global__ void k_convert13(const float* __restrict__ s1, const float* __restrict__ s3, int n4) {
    int i = blockIdx.x * blockDim.x + threadIdx.x;
    const float* src; __half2* d;
    if (i < n4)           { src = s1; d = (__half2*)g_sw1h; }
    else if (i < 2 * n4)  { src = s3; d = (__half2*)g_sw3h; i -= n4; }
    else return;
    float4 v = ((const float4*)src)[i];
    d[2 * i]     = __floats2half2_rn(v.x, v.y);
    d[2 * i + 1] = __floats2half2_rn(v.z, v.w);
}

// ---------------- stage fills (BK=64, BN=256) ----------------
// A: 128x64 halfs = 1024 x 16B chunks (4 per thread)
// B: 64x256 halfs = 2048 x 16B chunks (8 per thread)
__device__ __forceinline__ void fill_stage(
    const __half* __restrict__ A, int strideA,
    const __half* __restrict__ B, int ldb,
    int m0, int n0, int kt, __half* Asb, __half* Bsb, int tid)
{
#pragma unroll
    for (int i = 0; i < 4; i++) {
        int c = tid + i * 256;
        int ar = c >> 3, ac = c & 7;
        cp16(Asb + ar * ASTR + ac * 8,
             A + (size_t)(m0 + ar) * strideA + kt * BK + ac * 8);
    }
#pragma unroll
    for (int i = 0; i < 8; i++) {
        int c = tid + i * 256;
        int br = c >> 5, bc = c & 31;
        cp16(Bsb + br * BSTR + bc * 8,
             B + (size_t)(kt * BK + br) * ldb + n0 + bc * 8);
    }
}
// up-fused: B rows hold [sw1 cols n0..n0+127 | sw3 cols n0..n0+127]
__device__ __forceinline__ void fill_stage_up(
    int kt, int m0, int n0, __half* Asb, __half* Bsb, int tid)
{
#pragma unroll
    for (int i = 0; i < 4; i++) {
        int c = tid + i * 256;
        int ar = c >> 3, ac = c & 7;
        cp16(Asb + ar * ASTR + ac * 8,
             g_xh + (size_t)(m0 + ar) * C_DIM + kt * BK + ac * 8);
    }
#pragma unroll
    for (int i = 0; i < 8; i++) {
        int c = tid + i * 256;
        int br = c >> 5, bc = c & 31;
        if (bc < 16)
            cp16(Bsb + br * BSTR + bc * 8,
                 g_sw1h + (size_t)(kt * BK + br) * HS + n0 + bc * 8);
        else
            cp16(Bsb + br * BSTR + 128 + (bc - 16) * 8,
                 g_sw3h + (size_t)(kt * BK + br) * HS + n0 + (bc - 16) * 8);
    }
}

// ---------------- 64x64 warp-tile compute (acc[4][8][4]) ----------------
__device__ __forceinline__ void compute_stage(
    const __half* As, const __half* Bs, float acc[4][8][4],
    int wm, int wn, int lane)
{
#pragma unroll
    for (int ks = 0; ks < 4; ks++) {
        uint32_t a[4][4];
#pragma unroll
        for (int mi = 0; mi < 4; mi++) {
            const __half* p = &As[(wm * 64 + mi * 16 + (lane & 15)) * ASTR
                                  + ks * 16 + (lane >> 4) * 8];
            ldsm4(a[mi], p);
        }
        const int brow = (ks * 16 + (lane & 7) + ((lane >> 3) & 1) * 8) * BSTR
                         + (lane >> 4) * 8;
#pragma unroll
        for (int p4 = 0; p4 < 4; p4++) {
            uint32_t b[4];
            ldsm4t(b, &Bs[brow + wn * 64 + p4 * 16]);
#pragma unroll
            for (int mi = 0; mi < 4; mi++) {
                mma16816(acc[mi][2 * p4 + 0], a[mi], &b[0]);
                mma16816(acc[mi][2 * p4 + 1], a[mi], &b[2]);
            }
        }
    }
}

// ================= merged UP kernel ==========================================
// 1D grid, 6144 CTAs:
//   bid < 4096 : shared-up (128 rows x 128 H2-cols, both branches; = 128x256 MMA)
//   bid >= 4096: routed-up (128x256, gelu)
__global__ __launch_bounds__(256, 1) void k_up_all(
    const float* __restrict__ sb1, const float* __restrict__ sb3,
    const float* __restrict__ b1)
{
    extern __shared__ __align__(16) __half smem[];
    __half* Asm = smem;
    __half* Bsm = smem + NSTG * A_ST;

    const int tid = threadIdx.x;
    const int bid = blockIdx.x;
    const int warp = tid >> 5, lane = tid & 31;
    const int KT = C_DIM / BK;                 // 16

    if (bid < 4096) {
        // ---------- shared up: H2 = silu(x@sw1+b1)*(x@sw3+b3) ----------
        const int m0 = (bid >> 4) * BM;
        const int n0 = (bid & 15) * 128;
        // warp tile: 64 rows x 32 cols PER BRANCH; wm 0..1, wn 0..3
        const int wm = warp & 1, wn = warp >> 1;

#pragma unroll
        for (int c = 0; c < NSTG - 1; c++) {
            fill_stage_up(c, m0, n0, Asm + c * A_ST, Bsm + c * B_ST, tid);
            asm volatile("cp.async.commit_group;");
        }

        float acc1[4][4][4], acc3[4][4][4];
#pragma unroll
        for (int i = 0; i < 4; i++)
#pragma unroll
            for (int j = 0; j < 4; j++)
#pragma unroll
                for (int e = 0; e < 4; e++) { acc1[i][j][e] = 0.f; acc3[i][j][e] = 0.f; }

        int s = 0, fs = NSTG - 1;
        for (int kt = 0; kt < KT; ++kt) {
            asm volatile("cp.async.wait_group %0;" :: "n"(NSTG - 2));
            __syncthreads();

            const __half* As = Asm + s * A_ST;
            const __half* Bs = Bsm + s * B_ST;
#pragma unroll
            for (int ks = 0; ks < 4; ks++) {
                uint32_t a[4][4];
#pragma unroll
                for (int mi = 0; mi < 4; mi++) {
                    const __half* p = &As[(wm * 64 + mi * 16 + (lane & 15)) * ASTR
                                          + ks * 16 + (lane >> 4) * 8];
                    ldsm4(a[mi], p);
                }
                const int brow = (ks * 16 + (lane & 7) + ((lane >> 3) & 1) * 8) * BSTR
                                 + (lane >> 4) * 8;
#pragma unroll
                for (int p4 = 0; p4 < 2; p4++) {       // branch 1: cols wn*32+p4*16
                    uint32_t b[4];
                    ldsm4t(b, &Bs[brow + wn * 32 + p4 * 16]);
#pragma unroll
                    for (int mi = 0; mi < 4; mi++) {
                        mma16816(acc1[mi][2 * p4 + 0], a[mi], &b[0]);
                        mma16816(acc1[mi][2 * p4 + 1], a[mi], &b[2]);
                    }
                }
#pragma unroll
                for (int p4 = 0; p4 < 2; p4++) {       // branch 3: +128 col offset
                    uint32_t b[4];
                    ldsm4t(b, &Bs[brow + 128 + wn * 32 + p4 * 16]);
#pragma unroll
                    for (int mi = 0; mi < 4; mi++) {
                        mma16816(acc3[mi][2 * p4 + 0], a[mi], &b[0]);
                        mma16816(acc3[mi][2 * p4 + 1], a[mi], &b[2]);
                    }
                }
            }

            if (kt + NSTG - 1 < KT)
                fill_stage_up(kt + NSTG - 1, m0, n0,
                              Asm + fs * A_ST, Bsm + fs * B_ST, tid);
            asm volatile("cp.async.commit_group;");

            if (++s == NSTG) s = 0;
            if (++fs == NSTG) fs = 0;
        }

#pragma unroll
        for (int mi = 0; mi < 4; mi++)
#pragma unroll
            for (int ni = 0; ni < 4; ni++)
#pragma unroll
                for (int pp = 0; pp < 2; pp++) {
                    int row = m0 + wm * 64 + mi * 16 + (lane >> 2) + pp * 8;
                    int col = n0 + wn * 32 + ni * 8 + (lane & 3) * 2;
                    float u0 = acc1[mi][ni][2 * pp + 0] + sb1[col];
                    float u1 = acc1[mi][ni][2 * pp + 1] + sb1[col + 1];
                    float w0 = acc3[mi][ni][2 * pp + 0] + sb3[col];
                    float w1 = acc3[mi][ni][2 * pp + 1] + sb3[col + 1];
                    float v0 = u0 / (1.f + __expf(-u0)) * w0;
                    float v1 = u1 / (1.f + __expf(-u1)) * w1;
                    *(__half2*)(g_H2 + (size_t)row * HS + col) = __floats2half2_rn(v0, v1);
                }
    } else {
        // ---------- routed up: Hr[z] = gelu(x_perm[rr block] @ w1[e] + b1[e]) ------
        const int rid = bid - 4096;
        const int z = rid >> 7;               // 128 CTAs per z (32 m x 4 n)
        const int rr = z & 7, kk = z >> 3;
        const int e = (3 * rr + 7 * kk) & 7;
        const int m0 = ((rid >> 2) & 31) * BM;
        const int n0 = (rid & 3) * BN;
        const __half* A = g_xh + (size_t)rr * 4096 * C_DIM;
        const __half* B = g_w1h + (size_t)e * C_DIM * HR;
        __half* outp = g_Hr + (size_t)z * 4096 * HR;
        const float* bias = b1 + e * HR;
        const int wm = warp & 1, wn = warp >> 1;

#pragma unroll
        for (int c = 0; c < NSTG - 1; c++) {
            fill_stage(A, C_DIM, B, HR, m0, n0, c,
                       Asm + c * A_ST, Bsm + c * B_ST, tid);
            asm volatile("cp.async.commit_group;");
        }

        float acc[4][8][4];
#pragma unroll
        for (int i = 0; i < 4; i++)
#pragma unroll
            for (int j = 0; j < 8; j++)
#pragma unroll
                for (int ee = 0; ee < 4; ee++) acc[i][j][ee] = 0.f;

        int s = 0, fs = NSTG - 1;
        for (int kt = 0; kt < KT; ++kt) {
            asm volatile("cp.async.wait_group %0;" :: "n"(NSTG - 2));
            __syncthreads();

            compute_stage(Asm + s * A_ST, Bsm + s * B_ST, acc, wm, wn, lane);

            if (kt + NSTG - 1 < KT)
                fill_stage(A, C_DIM, B, HR, m0, n0, kt + NSTG - 1,
                           Asm + fs * A_ST, Bsm + fs * B_ST, tid);
            asm volatile("cp.async.commit_group;");

            if (++s == NSTG) s = 0;
            if (++fs == NSTG) fs = 0;
        }

#pragma unroll
        for (int mi = 0; mi < 4; mi++)
#pragma unroll
            for (int ni = 0; ni < 8; ni++)
#pragma unroll
                for (int pp = 0; pp < 2; pp++) {
                    int row = m0 + wm * 64 + mi * 16 + (lane >> 2) + pp * 8;
                    int col = n0 + wn * 64 + ni * 8 + (lane & 3) * 2;
                    float v0 = acc[mi][ni][2 * pp + 0] + bias[col];
                    float v1 = acc[mi][ni][2 * pp + 1] + bias[col + 1];
                    v0 = 0.5f * v0 * (1.f + erff(v0 * 0.70710678118654752f));
                    v1 = 0.5f * v1 * (1.f + erff(v1 * 0.70710678118654752f));
                    *(__half2*)(outp + (size_t)row * HR + col) = __floats2half2_rn(v0, v1);
                }
    }
}

// ---------------- mega down kernel: out = 0.5*shared_down + 0.25*(y0+y1) ------
// Three K-segments (BK=64), all contiguous A in permuted space:
//   kt [0,32):  H2_perm[rr block] @ (0.5*sw2)
//   kt [32,48): Hr[rr]   @ (0.25*w2[e0])
//   kt [48,64): Hr[8+rr] @ (0.25*w2[e1])
#define KT_MEGA 64
__device__ __forceinline__ void mega_map(int kt, int rr, int e0, int e1,
                                         const __half*& Ap, int& sA, const __half*& Bp) {
    if (kt < 32) {
        Ap = g_H2 + (size_t)rr * 4096 * HS + (size_t)kt * BK;
        sA = HS;
        Bp = g_sw2h + (size_t)kt * BK * C_DIM;
    } else if (kt < 48) {
        Ap = g_Hr + (size_t)rr * 4096 * HR + (size_t)(kt - 32) * BK;
        sA = HR;
        Bp = g_w2h + (size_t)e0 * HR * C_DIM + (size_t)(kt - 32) * BK * C_DIM;
    } else {
        Ap = g_Hr + (size_t)(8 + rr) * 4096 * HR + (size_t)(kt - 48) * BK;
        sA = HR;
        Bp = g_w2h + (size_t)e1 * HR * C_DIM + (size_t)(kt - 48) * BK * C_DIM;
    }
}
__device__ __forceinline__ void fill_stage_mega(
    int kt, int rr, int e0, int e1, int m0, int n0,
    __half* Asb, __half* Bsb, int tid)
{
    const __half* Ap; const __half* Bp; int sA;
    mega_map(kt, rr, e0, e1, Ap, sA, Bp);
#pragma unroll
    for (int i = 0; i < 4; i++) {
        int c = tid + i * 256;
        int ar = c >> 3, ac = c & 7;
        cp16(Asb + ar * ASTR + ac * 8,
             Ap + (size_t)(m0 + ar) * sA + ac * 8);
    }
#pragma unroll
    for (int i = 0; i < 8; i++) {
        int c = tid + i * 256;
        int br = c >> 5, bc = c & 31;
        cp16(Bsb + br * BSTR + bc * 8,
             Bp + (size_t)br * C_DIM + n0 + bc * 8);
    }
}
__global__ __launch_bounds__(256, 1) void k_down_mega(
    const float* __restrict__ sb2, const float* __restrict__ b2,
    float* __restrict__ dout)
{
    extern __shared__ __align__(16) __half smem[];
    __half* Asm = smem;
    __half* Bsm = smem + NSTG * A_ST;

    const int rr = blockIdx.z;
    const int e0 = (3 * rr) & 7;
    const int e1 = (3 * rr + 7) & 7;
    const int tid = threadIdx.x;
    const int m0 = blockIdx.y * BM;
    const int n0 = blockIdx.x * BN;

#pragma unroll
    for (int c = 0; c < NSTG - 1; c++) {
        fill_stage_mega(c, rr, e0, e1, m0, n0,
                        Asm + c * A_ST, Bsm + c * B_ST, tid);
        asm volatile("cp.async.commit_group;");
    }

    float acc[4][8][4];
#pragma unroll
    for (int i = 0; i < 4; i++)
#pragma unroll
        for (int j = 0; j < 8; j++)
#pragma unroll
            for (int e = 0; e < 4; e++) acc[i][j][e] = 0.f;

    const int warp = tid >> 5, lane = tid & 31;
    const int wm = warp & 1, wn = warp >> 1;

    int s = 0, fs = NSTG - 1;
    for (int kt = 0; kt < KT_MEGA; ++kt) {
        asm volatile("cp.async.wait_group %0;" :: "n"(NSTG - 2));
        __syncthreads();

        compute_stage(Asm + s * A_ST, Bsm + s * B_ST, acc, wm, wn, lane);

        if (kt + NSTG - 1 < KT_MEGA)
            fill_stage_mega(kt + NSTG - 1, rr, e0, e1, m0, n0,
                            Asm + fs * A_ST, Bsm + fs * B_ST, tid);
        asm volatile("cp.async.commit_group;");

        if (++s == NSTG) s = 0;
        if (++fs == NSTG) fs = 0;
    }

    // epilogue: single fp32 write, combined bias, un-permute rows
#pragma unroll
    for (int mi = 0; mi < 4; mi++)
#pragma unroll
        for (int ni = 0; ni < 8; ni++)
#pragma unroll
            for (int pp = 0; pp < 2; pp++) {
                int rowl = m0 + wm * 64 + mi * 16 + (lane >> 2) + pp * 8;
                int col  = n0 + wn * 64 + ni * 8 + (lane & 3) * 2;
                float bb0 = 0.5f * sb2[col]
                          + 0.25f * (b2[e0 * C_DIM + col] + b2[e1 * C_DIM + col]);
                float bb1 = 0.5f * sb2[col + 1]
                          + 0.25f * (b2[e0 * C_DIM + col + 1] + b2[e1 * C_DIM + col + 1]);
                float2 f;
                f.x = acc[mi][ni][2 * pp + 0] + bb0;
                f.y = acc[mi][ni][2 * pp + 1] + bb1;
                size_t t = (size_t)rr + 8 * (size_t)rowl;    // actual token
                *(float2*)(dout + t * C_DIM + col) = f;
            }
}

// ---------------- launch ----------------
extern "C" void kernel_launch(void* const* d_in, const int* in_sizes, int n_in,
                              void* d_out, int out_size) {
    const float* x   = (const float*)d_in[0];
    // d_in[1] = t_emb : unused by reference
    const float* sw1 = (const float*)d_in[2];
    const float* sb1 = (const float*)d_in[3];
    const float* sw3 = (const float*)d_in[4];
    const float* sb3 = (const float*)d_in[5];
    const float* sw2 = (const float*)d_in[6];
    const float* sb2 = (const float*)d_in[7];
    const float* w1  = (const float*)d_in[8];
    const float* b1  = (const float*)d_in[9];
    const float* w2  = (const float*)d_in[10];
    const float* b2  = (const float*)d_in[11];
    float* out = (float*)d_out;

    cudaFuncSetAttribute(k_up_all,    cudaFuncAttributeMaxDynamicSharedMemorySize, SMEM_BYTES);
    cudaFuncSetAttribute(k_down_mega, cudaFuncAttributeMaxDynamicSharedMemorySize, SMEM_BYTES);

    // fp32 -> fp16 conversions; x permuted residue-major;
    // down-proj weights pre-scaled (0.5 shared, 0.25 routed)
    {
        int n4x = (N_TOK * C_DIM) / 4;
        k_convx<<<(n4x + 255) / 256, 256>>>(x, n4x);
        int n4w = (C_DIM * HS) / 4;
        k_convert13<<<(2 * n4w + 255) / 256, 256>>>(sw1, sw3, n4w);
        k_convert<<<(n4w + 255) / 256, 256>>>(sw2, 3, n4w, 0.5f);
        int n4e = (NE * C_DIM * HR) / 4;
        k_convert<<<(n4e + 255) / 256, 256>>>(w1, 4, n4e, 1.0f);
        k_convert<<<(n4e + 255) / 256, 256>>>(w2, 5, n4e, 0.25f);
    }

    // merged up path: shared SwiGLU (4096 CTAs) + routed gelu (2048 CTAs)
    k_up_all<<<6144, 256, SMEM_BYTES>>>(sb1, sb3, b1);

    // fused down path: single pass, single out write
    k_down_mega<<<dim3(C_DIM / BN, 4096 / BM, 8), 256, SMEM_BYTES>>>(sb2, b2, out);
}

// round 13
// speedup vs baseline: 1.0168x; 1.0168x over previous
#include <cuda_runtime.h>
#include <cuda_fp16.h>
#include <stdint.h>
#include <math.h>

// ---------------- problem constants ----------------
#define N_TOK 32768      // B*T = 4*8192
#define C_DIM 1024
#define HS    2048
#define HR    1024
#define NE    8

// Token permutation: physical row = (t & 7) * 4096 + (t >> 3)  (residue-major).

// ---------------- GEMM tile config (validated round-11 optimum) ----------------
#define BM 128
#define BN 128
#define BK 64
#define NSTG 3
#define ASTR (BK + 8)    // 72 halfs/row (144B, conflict-free ldmatrix)
#define BSTR (BN + 8)    // 136 halfs/row (272B, conflict-free ldmatrix.trans)
#define A_ST (BM * ASTR)             // 9216 halfs per A stage
#define B_ST (BK * BSTR)             // 8704 halfs per B stage
#define SMEM_BYTES (NSTG * (A_ST + B_ST) * 2)   // 107520 B -> 2 CTAs/SM

// ---------------- static scratch (no allocations allowed) ----------------
__device__ __half g_xh[N_TOK * C_DIM];          // x fp16, residue-major permuted
__device__ __half g_sw1h[C_DIM * HS];
__device__ __half g_sw3h[C_DIM * HS];
__device__ __half g_sw2h[HS * C_DIM];           // pre-scaled by 0.5
__device__ __half g_w1h[NE * C_DIM * HR];
__device__ __half g_w2h[NE * HR * C_DIM];       // pre-scaled by 0.25
__device__ __half g_H2[N_TOK * HS];             // swiglu hidden, permuted rows
__device__ __half g_Hr[2 * N_TOK * HR];         // routed hidden [k*8+r][4096][HR]
__device__ float  g_biasD[NE * C_DIM];          // combined down bias per residue

// ---------------- small PTX helpers ----------------
__device__ __forceinline__ void cp16(void* s, const void* g) {
    unsigned sa = (unsigned)__cvta_generic_to_shared(s);
    asm volatile("cp.async.cg.shared.global [%0], [%1], 16;" :: "r"(sa), "l"(g));
}
__device__ __forceinline__ void ldsm4(uint32_t* r, const __half* p) {
    unsigned a = (unsigned)__cvta_generic_to_shared(p);
    asm volatile("ldmatrix.sync.aligned.m8n8.x4.shared.b16 {%0,%1,%2,%3}, [%4];"
                 : "=r"(r[0]), "=r"(r[1]), "=r"(r[2]), "=r"(r[3]) : "r"(a));
}
__device__ __forceinline__ void ldsm4t(uint32_t* r, const __half* p) {
    unsigned a = (unsigned)__cvta_generic_to_shared(p);
    asm volatile("ldmatrix.sync.aligned.m8n8.x4.trans.shared.b16 {%0,%1,%2,%3}, [%4];"
                 : "=r"(r[0]), "=r"(r[1]), "=r"(r[2]), "=r"(r[3]) : "r"(a));
}
__device__ __forceinline__ void mma16816(float* d, const uint32_t* a, const uint32_t* b) {
    asm volatile(
        "mma.sync.aligned.m16n8k16.row.col.f32.f16.f16.f32 "
        "{%0,%1,%2,%3},{%4,%5,%6,%7},{%8,%9},{%0,%1,%2,%3};"
        : "+f"(d[0]), "+f"(d[1]), "+f"(d[2]), "+f"(d[3])
        : "r"(a[0]), "r"(a[1]), "r"(a[2]), "r"(a[3]), "r"(b[0]), "r"(b[1]));
}

// ---------------- merged conversion kernel (one launch, all tensors) -----------
#define CV_NX ((N_TOK * C_DIM) / 4)     // 8388608
#define CV_NW ((C_DIM * HS) / 4)        // 524288
#define CV_NE ((NE * C_DIM * HR) / 4)   // 2097152
#define CV_TOTAL (CV_NX + 3 * CV_NW + 2 * CV_NE)   // 14155776

__global__ void k_convall(
    const float* __restrict__ x,
    const float* __restrict__ sw1, const float* __restrict__ sw3,
    const float* __restrict__ sw2,
    const float* __restrict__ w1,  const float* __restrict__ w2)
{
    int i = blockIdx.x * blockDim.x + threadIdx.x;
    if (i >= CV_TOTAL) return;
    if (i < CV_NX) {
        // x with residue-major row permutation
        int t = i >> 8;                  // 256 float4 per row
        int c = i & 255;
        int pr = ((t & 7) << 12) | (t >> 3);
        float4 v = ((const float4*)x)[i];
        __half2* d = (__half2*)g_xh + (size_t)pr * (C_DIM / 2) + c * 2;
        d[0] = __floats2half2_rn(v.x, v.y);
        d[1] = __floats2half2_rn(v.z, v.w);
        return;
    }
    i -= CV_NX;
    const float* src; __half2* d; float sc;
    if (i < CV_NW)               { src = sw1; d = (__half2*)g_sw1h; sc = 1.0f; }
    else if (i < 2 * CV_NW)      { src = sw3; d = (__half2*)g_sw3h; sc = 1.0f; i -= CV_NW; }
    else if (i < 3 * CV_NW)      { src = sw2; d = (__half2*)g_sw2h; sc = 0.5f; i -= 2 * CV_NW; }
    else if (i < 3 * CV_NW + CV_NE) { src = w1; d = (__half2*)g_w1h; sc = 1.0f; i -= 3 * CV_NW; }
    else                         { src = w2; d = (__half2*)g_w2h; sc = 0.25f; i -= 3 * CV_NW + CV_NE; }
    float4 v = ((const float4*)src)[i];
    d[2 * i]     = __floats2half2_rn(v.x * sc, v.y * sc);
    d[2 * i + 1] = __floats2half2_rn(v.z * sc, v.w * sc);
}

// combined down bias: g_biasD[rr][col] = 0.5*sb2 + 0.25*(b2[e0]+b2[e1])
__global__ void k_bias(const float* __restrict__ sb2, const float* __restrict__ b2) {
    int i = blockIdx.x * blockDim.x + threadIdx.x;
    if (i >= NE * C_DIM) return;
    int rr = i >> 10, col = i & 1023;
    int e0 = (3 * rr) & 7;
    int e1 = (3 * rr + 7) & 7;
    g_biasD[i] = 0.5f * sb2[col]
               + 0.25f * (b2[e0 * C_DIM + col] + b2[e1 * C_DIM + col]);
}

// ---------------- generic stage fill (BK=64, cp.async) ----------------
__device__ __forceinline__ void fill_stage(
    const __half* __restrict__ A, int strideA,
    const __half* __restrict__ B, int ldb,
    int m0, int n0, int kt, __half* Asb, __half* Bsb, int tid)
{
#pragma unroll
    for (int i = 0; i < 4; i++) {              // A: 128x64 halfs = 1024 x 16B chunks
        int c = tid + i * 256;
        int ar = c >> 3, ac = c & 7;
        cp16(Asb + ar * ASTR + ac * 8,
             A + (size_t)(m0 + ar) * strideA + kt * BK + ac * 8);
    }
#pragma unroll
    for (int i = 0; i < 4; i++) {              // B: 64x128 halfs = 1024 x 16B chunks
        int c = tid + i * 256;
        int br = c >> 4, bc = c & 15;
        cp16(Bsb + br * BSTR + bc * 8,
             B + (size_t)(kt * BK + br) * ldb + n0 + bc * 8);
    }
}

// ---------------- warp-tile compute on one resident stage (128x128, BK=64) ----------
__device__ __forceinline__ void compute_stage(
    const __half* As, const __half* Bs, float acc[2][8][4],
    int wm, int wn, int lane)
{
#pragma unroll
    for (int ks = 0; ks < 4; ks++) {           // four k16 steps per BK=64
        uint32_t a[2][4];
#pragma unroll
        for (int mi = 0; mi < 2; mi++) {
            const __half* p = &As[(wm * 32 + mi * 16 + (lane & 15)) * ASTR
                                  + ks * 16 + (lane >> 4) * 8];
            ldsm4(a[mi], p);
        }
#pragma unroll
        for (int p4 = 0; p4 < 4; p4++) {       // 16 cols per ldmatrix.x4.trans
            uint32_t b[4];
            const __half* p = &Bs[(ks * 16 + (lane & 7) + ((lane >> 3) & 1) * 8) * BSTR
                                  + wn * 64 + p4 * 16 + (lane >> 4) * 8];
            ldsm4t(b, p);
            mma16816(acc[0][2 * p4 + 0], a[0], &b[0]);
            mma16816(acc[0][2 * p4 + 1], a[0], &b[2]);
            mma16816(acc[1][2 * p4 + 0], a[1], &b[0]);
            mma16816(acc[1][2 * p4 + 1], a[1], &b[2]);
        }
    }
}

// ---------------- up-fused stage fill: A=x(perm), B=[sw1 64cols | sw3 64cols] -----
__device__ __forceinline__ void fill_stage_up(
    int kt, int m0, int n0, __half* Asb, __half* Bsb, int tid)
{
#pragma unroll
    for (int i = 0; i < 4; i++) {              // A: 128x64 halfs
        int c = tid + i * 256;
        int ar = c >> 3, ac = c & 7;
        cp16(Asb + ar * ASTR + ac * 8,
             g_xh + (size_t)(m0 + ar) * C_DIM + kt * BK + ac * 8);
    }
#pragma unroll
    for (int i = 0; i < 4; i++) {              // B: 64 rows x (64|64) halfs
        int c = tid + i * 256;
        int br = c >> 4, bc = c & 15;
        if (bc < 8)
            cp16(Bsb + br * BSTR + bc * 8,
                 g_sw1h + (size_t)(kt * BK + br) * HS + n0 + bc * 8);
        else
            cp16(Bsb + br * BSTR + 64 + (bc - 8) * 8,
                 g_sw3h + (size_t)(kt * BK + br) * HS + n0 + (bc - 8) * 8);
    }
}

// ================= merged UP kernel ==========================================
// 1D grid, 12288 CTAs:
//   bid < 8192 : shared-up tile (128 permuted rows x 64 H2-cols, both branches)
//   bid >= 8192: routed-up tile (128x128, gelu)
__global__ __launch_bounds__(256, 2) void k_up_all(
    const float* __restrict__ sb1, const float* __restrict__ sb3,
    const float* __restrict__ b1)
{
    extern __shared__ __align__(16) __half smem[];
    __half* Asm = smem;
    __half* Bsm = smem + NSTG * A_ST;

    const int tid = threadIdx.x;
    const int bid = blockIdx.x;
    const int warp = tid >> 5, lane = tid & 31;
    const int KT = C_DIM / BK;                 // 16

    if (bid < 8192) {
        // ---------- shared up: H2 = silu(x@sw1+b1)*(x@sw3+b3) ----------
        const int m0 = (bid >> 5) * BM;
        const int n0 = (bid & 31) * 64;
        const int wm = warp & 3, wn = (warp >> 2) & 1;

#pragma unroll
        for (int c = 0; c < NSTG - 1; c++) {
            fill_stage_up(c, m0, n0, Asm + c * A_ST, Bsm + c * B_ST, tid);
            asm volatile("cp.async.commit_group;");
        }

        float acc1[2][4][4], acc3[2][4][4];
#pragma unroll
        for (int i = 0; i < 2; i++)
#pragma unroll
            for (int j = 0; j < 4; j++)
#pragma unroll
                for (int e = 0; e < 4; e++) { acc1[i][j][e] = 0.f; acc3[i][j][e] = 0.f; }

        int s = 0, fs = NSTG - 1;
        for (int kt = 0; kt < KT; ++kt) {
            asm volatile("cp.async.wait_group %0;" :: "n"(NSTG - 2));
            __syncthreads();

            // fill FIRST (stage fs was consumed last iter; sync above made it safe)
            if (kt + NSTG - 1 < KT)
                fill_stage_up(kt + NSTG - 1, m0, n0,
                              Asm + fs * A_ST, Bsm + fs * B_ST, tid);
            asm volatile("cp.async.commit_group;");

            const __half* As = Asm + s * A_ST;
            const __half* Bs = Bsm + s * B_ST;
#pragma unroll
            for (int ks = 0; ks < 4; ks++) {
                uint32_t a[2][4];
#pragma unroll
                for (int mi = 0; mi < 2; mi++) {
                    const __half* p = &As[(wm * 32 + mi * 16 + (lane & 15)) * ASTR
                                          + ks * 16 + (lane >> 4) * 8];
                    ldsm4(a[mi], p);
                }
                const int brow = (ks * 16 + (lane & 7) + ((lane >> 3) & 1) * 8) * BSTR
                                 + (lane >> 4) * 8;
#pragma unroll
                for (int p4 = 0; p4 < 2; p4++) {   // branch 1 (sw1)
                    uint32_t b[4];
                    ldsm4t(b, &Bs[brow + wn * 32 + p4 * 16]);
                    mma16816(acc1[0][2 * p4 + 0], a[0], &b[0]);
                    mma16816(acc1[0][2 * p4 + 1], a[0], &b[2]);
                    mma16816(acc1[1][2 * p4 + 0], a[1], &b[0]);
                    mma16816(acc1[1][2 * p4 + 1], a[1], &b[2]);
                }
#pragma unroll
                for (int p4 = 0; p4 < 2; p4++) {   // branch 3 (sw3): +64 col offset
                    uint32_t b[4];
                    ldsm4t(b, &Bs[brow + 64 + wn * 32 + p4 * 16]);
                    mma16816(acc3[0][2 * p4 + 0], a[0], &b[0]);
                    mma16816(acc3[0][2 * p4 + 1], a[0], &b[2]);
                    mma16816(acc3[1][2 * p4 + 0], a[1], &b[0]);
                    mma16816(acc3[1][2 * p4 + 1], a[1], &b[2]);
                }
            }

            if (++s == NSTG) s = 0;
            if (++fs == NSTG) fs = 0;
        }

#pragma unroll
        for (int mi = 0; mi < 2; mi++)
#pragma unroll
            for (int ni = 0; ni < 4; ni++)
#pragma unroll
                for (int pp = 0; pp < 2; pp++) {
                    int row = m0 + wm * 32 + mi * 16 + (lane >> 2) + pp * 8;
                    int col = n0 + wn * 32 + ni * 8 + (lane & 3) * 2;
                    float u0 = acc1[mi][ni][2 * pp + 0] + sb1[col];
                    float u1 = acc1[mi][ni][2 * pp + 1] + sb1[col + 1];
                    float w0 = acc3[mi][ni][2 * pp + 0] + sb3[col];
                    float w1 = acc3[mi][ni][2 * pp + 1] + sb3[col + 1];
                    float v0 = u0 / (1.f + __expf(-u0)) * w0;
                    float v1 = u1 / (1.f + __expf(-u1)) * w1;
                    *(__half2*)(g_H2 + (size_t)row * HS + col) = __floats2half2_rn(v0, v1);
                }
    } else {
        // ---------- routed up: Hr[z] = gelu(x_perm[rr block] @ w1[e] + b1[e]) ------
        const int rid = bid - 8192;
        const int z = rid >> 8;               // 0..15, z = kk*8 + rr
        const int rr = z & 7, kk = z >> 3;
        const int e = (3 * rr + 7 * kk) & 7;
        const int m0 = ((rid >> 3) & 31) * BM;
        const int n0 = (rid & 7) * BN;
        const __half* A = g_xh + (size_t)rr * 4096 * C_DIM;   // contiguous rows
        const __half* B = g_w1h + (size_t)e * C_DIM * HR;
        __half* outp = g_Hr + (size_t)z * 4096 * HR;
        const float* bias = b1 + e * HR;
        const int wm = warp & 3, wn = warp >> 2;

#pragma unroll
        for (int c = 0; c < NSTG - 1; c++) {
            fill_stage(A, C_DIM, B, HR, m0, n0, c,
                       Asm + c * A_ST, Bsm + c * B_ST, tid);
            asm volatile("cp.async.commit_group;");
        }

        float acc[2][8][4];
#pragma unroll
        for (int i = 0; i < 2; i++)
#pragma unroll
            for (int j = 0; j < 8; j++)
#pragma unroll
                for (int ee = 0; ee < 4; ee++) acc[i][j][ee] = 0.f;

        int s = 0, fs = NSTG - 1;
        for (int kt = 0; kt < KT; ++kt) {
            asm volatile("cp.async.wait_group %0;" :: "n"(NSTG - 2));
            __syncthreads();

            if (kt + NSTG - 1 < KT)
                fill_stage(A, C_DIM, B, HR, m0, n0, kt + NSTG - 1,
                           Asm + fs * A_ST, Bsm + fs * B_ST, tid);
            asm volatile("cp.async.commit_group;");

            compute_stage(Asm + s * A_ST, Bsm + s * B_ST, acc, wm, wn, lane);

            if (++s == NSTG) s = 0;
            if (++fs == NSTG) fs = 0;
        }

#pragma unroll
        for (int mi = 0; mi < 2; mi++)
#pragma unroll
            for (int ni = 0; ni < 8; ni++)
#pragma unroll
                for (int pp = 0; pp < 2; pp++) {
                    int row = m0 + wm * 32 + mi * 16 + (lane >> 2) + pp * 8;
                    int col = n0 + wn * 64 + ni * 8 + (lane & 3) * 2;
                    float v0 = acc[mi][ni][2 * pp + 0] + bias[col];
                    float v1 = acc[mi][ni][2 * pp + 1] + bias[col + 1];
                    v0 = 0.5f * v0 * (1.f + erff(v0 * 0.70710678118654752f));
                    v1 = 0.5f * v1 * (1.f + erff(v1 * 0.70710678118654752f));
                    *(__half2*)(outp + (size_t)row * HR + col) = __floats2half2_rn(v0, v1);
                }
    }
}

// ---------------- mega down kernel: out = 0.5*shared_down + 0.25*(y0+y1) ------
// Three K-segments (BK=64), all contiguous A in permuted space:
//   kt [0,32):  H2_perm[rr block] @ (0.5*sw2)
//   kt [32,48): Hr[rr]   @ (0.25*w2[e0])
//   kt [48,64): Hr[8+rr] @ (0.25*w2[e1])
#define KT_MEGA 64
__device__ __forceinline__ void mega_map(int kt, int rr, int e0, int e1,
                                         const __half*& Ap, int& sA, const __half*& Bp) {
    if (kt < 32) {
        Ap = g_H2 + (size_t)rr * 4096 * HS + (size_t)kt * BK;
        sA = HS;
        Bp = g_sw2h + (size_t)kt * BK * C_DIM;
    } else if (kt < 48) {
        Ap = g_Hr + (size_t)rr * 4096 * HR + (size_t)(kt - 32) * BK;
        sA = HR;
        Bp = g_w2h + (size_t)e0 * HR * C_DIM + (size_t)(kt - 32) * BK * C_DIM;
    } else {
        Ap = g_Hr + (size_t)(8 + rr) * 4096 * HR + (size_t)(kt - 48) * BK;
        sA = HR;
        Bp = g_w2h + (size_t)e1 * HR * C_DIM + (size_t)(kt - 48) * BK * C_DIM;
    }
}
__device__ __forceinline__ void fill_stage_mega(
    int kt, int rr, int e0, int e1, int m0, int n0,
    __half* Asb, __half* Bsb, int tid)
{
    const __half* Ap; const __half* Bp; int sA;
    mega_map(kt, rr, e0, e1, Ap, sA, Bp);
#pragma unroll
    for (int i = 0; i < 4; i++) {
        int c = tid + i * 256;
        int ar = c >> 3, ac = c & 7;
        cp16(Asb + ar * ASTR + ac * 8,
             Ap + (size_t)(m0 + ar) * sA + ac * 8);
    }
#pragma unroll
    for (int i = 0; i < 4; i++) {
        int c = tid + i * 256;
        int br = c >> 4, bc = c & 15;
        cp16(Bsb + br * BSTR + bc * 8,
             Bp + (size_t)br * C_DIM + n0 + bc * 8);
    }
}
__global__ __launch_bounds__(256, 2) void k_down_mega(float* __restrict__ dout)
{
    extern __shared__ __align__(16) __half smem[];
    __half* Asm = smem;
    __half* Bsm = smem + NSTG * A_ST;

    const int rr = blockIdx.z;
    const int e0 = (3 * rr) & 7;
    const int e1 = (3 * rr + 7) & 7;
    const int tid = threadIdx.x;
    const int m0 = blockIdx.y * BM;
    const int n0 = blockIdx.x * BN;

#pragma unroll
    for (int c = 0; c < NSTG - 1; c++) {
        fill_stage_mega(c, rr, e0, e1, m0, n0,
                        Asm + c * A_ST, Bsm + c * B_ST, tid);
        asm volatile("cp.async.commit_group;");
    }

    float acc[2][8][4];
#pragma unroll
    for (int i = 0; i < 2; i++)
#pragma unroll
        for (int j = 0; j < 8; j++)
#pragma unroll
            for (int e = 0; e < 4; e++) acc[i][j][e] = 0.f;

    const int warp = tid >> 5, lane = tid & 31;
    const int wm = warp & 3, wn = warp >> 2;

    int s = 0, fs = NSTG - 1;
    for (int kt = 0; kt < KT_MEGA; ++kt) {
        asm volatile("cp.async.wait_group %0;" :: "n"(NSTG - 2));
        __syncthreads();

        if (kt + NSTG - 1 < KT_MEGA)
            fill_stage_mega(kt + NSTG - 1, rr, e0, e1, m0, n0,
                            Asm + fs * A_ST, Bsm + fs * B_ST, tid);
        asm volatile("cp.async.commit_group;");

        compute_stage(Asm + s * A_ST, Bsm + s * B_ST, acc, wm, wn, lane);

        if (++s == NSTG) s = 0;
        if (++fs == NSTG) fs = 0;
    }

    // epilogue: single fp32 write, precomputed combined bias, un-permute rows
    const float* biasD = g_biasD + rr * C_DIM;
#pragma unroll
    for (int mi = 0; mi < 2; mi++)
#pragma unroll
        for (int ni = 0; ni < 8; ni++)
#pragma unroll
            for (int pp = 0; pp < 2; pp++) {
                int rowl = m0 + wm * 32 + mi * 16 + (lane >> 2) + pp * 8;
                int col  = n0 + wn * 64 + ni * 8 + (lane & 3) * 2;
                float2 bb = *(const float2*)(biasD + col);
                float2 f;
                f.x = acc[mi][ni][2 * pp + 0] + bb.x;
                f.y = acc[mi][ni][2 * pp + 1] + bb.y;
                size_t t = (size_t)rr + 8 * (size_t)rowl;    // actual token
                *(float2*)(dout + t * C_DIM + col) = f;
            }
}

// ---------------- launch ----------------
extern "C" void kernel_launch(void* const* d_in, const int* in_sizes, int n_in,
                              void* d_out, int out_size) {
    const float* x   = (const float*)d_in[0];
    // d_in[1] = t_emb : unused by reference
    const float* sw1 = (const float*)d_in[2];
    const float* sb1 = (const float*)d_in[3];
    const float* sw3 = (const float*)d_in[4];
    const float* sb3 = (const float*)d_in[5];
    const float* sw2 = (const float*)d_in[6];
    const float* sb2 = (const float*)d_in[7];
    const float* w1  = (const float*)d_in[8];
    const float* b1  = (const float*)d_in[9];
    const float* w2  = (const float*)d_in[10];
    const float* b2  = (const float*)d_in[11];
    float* out = (float*)d_out;

    cudaFuncSetAttribute(k_up_all,    cudaFuncAttributeMaxDynamicSharedMemorySize, SMEM_BYTES);
    cudaFuncSetAttribute(k_down_mega, cudaFuncAttributeMaxDynamicSharedMemorySize, SMEM_BYTES);

    // one merged conversion launch + tiny bias kernel
    k_convall<<<(CV_TOTAL + 255) / 256, 256>>>(x, sw1, sw3, sw2, w1, w2);
    k_bias<<<(NE * C_DIM + 255) / 256, 256>>>(sb2, b2);

    // merged up path: shared SwiGLU (8192 CTAs) + routed gelu (4096 CTAs)
    k_up_all<<<12288, 256, SMEM_BYTES>>>(sb1, sb3, b1);

    // fused down path: single pass, single out write
    k_down_mega<<<dim3(C_DIM / BN, 4096 / BM, 8), 256, SMEM_BYTES>>>(out);
}

// round 14
// speedup vs baseline: 1.0966x; 1.0785x over previous
#include <cuda_runtime.h>
#include <cuda_fp16.h>
#include <stdint.h>
#include <math.h>

// ---------------- problem constants ----------------
#define N_TOK 32768      // B*T = 4*8192
#define C_DIM 1024
#define HS    2048
#define HR    1024
#define NE    8

// Token permutation: physical row = (t & 7) * 4096 + (t >> 3)  (residue-major).

// ---------------- GEMM tile config (validated round-11 optimum) ----------------
#define BM 128
#define BN 128
#define BK 64
#define NSTG 3
#define ASTR (BK + 8)    // 72 halfs/row (144B, conflict-free ldmatrix)
#define BSTR (BN + 8)    // 136 halfs/row (272B, conflict-free ldmatrix.trans)
#define A_ST (BM * ASTR)             // 9216 halfs per A stage
#define B_ST (BK * BSTR)             // 8704 halfs per B stage
#define SMEM_BYTES (NSTG * (A_ST + B_ST) * 2)   // 107520 B -> 2 CTAs/SM

// ---------------- static scratch (no allocations allowed) ----------------
__device__ __half g_xh[N_TOK * C_DIM];          // x fp16, residue-major permuted
__device__ __half g_sw1h[C_DIM * HS];
__device__ __half g_sw3h[C_DIM * HS];
__device__ __half g_sw2h[HS * C_DIM];           // pre-scaled by 0.5
__device__ __half g_w1h[NE * C_DIM * HR];
__device__ __half g_w2h[NE * HR * C_DIM];       // pre-scaled by 0.25
__device__ __half g_H2[N_TOK * HS];             // swiglu hidden, permuted rows
__device__ __half g_Hr[2 * N_TOK * HR];         // routed hidden [k*8+r][4096][HR]
__device__ float  g_biasD[NE * C_DIM];          // combined down bias per residue

// ---------------- small PTX helpers ----------------
__device__ __forceinline__ void cp16(void* s, const void* g) {
    unsigned sa = (unsigned)__cvta_generic_to_shared(s);
    asm volatile("cp.async.cg.shared.global [%0], [%1], 16;" :: "r"(sa), "l"(g));
}
__device__ __forceinline__ void ldsm4(uint32_t* r, const __half* p) {
    unsigned a = (unsigned)__cvta_generic_to_shared(p);
    asm volatile("ldmatrix.sync.aligned.m8n8.x4.shared.b16 {%0,%1,%2,%3}, [%4];"
                 : "=r"(r[0]), "=r"(r[1]), "=r"(r[2]), "=r"(r[3]) : "r"(a));
}
__device__ __forceinline__ void ldsm4t(uint32_t* r, const __half* p) {
    unsigned a = (unsigned)__cvta_generic_to_shared(p);
    asm volatile("ldmatrix.sync.aligned.m8n8.x4.trans.shared.b16 {%0,%1,%2,%3}, [%4];"
                 : "=r"(r[0]), "=r"(r[1]), "=r"(r[2]), "=r"(r[3]) : "r"(a));
}
__device__ __forceinline__ void mma16816(float* d, const uint32_t* a, const uint32_t* b) {
    asm volatile(
        "mma.sync.aligned.m16n8k16.row.col.f32.f16.f16.f32 "
        "{%0,%1,%2,%3},{%4,%5,%6,%7},{%8,%9},{%0,%1,%2,%3};"
        : "+f"(d[0]), "+f"(d[1]), "+f"(d[2]), "+f"(d[3])
        : "r"(a[0]), "r"(a[1]), "r"(a[2]), "r"(a[3]), "r"(b[0]), "r"(b[1]));
}

// ---------------- merged conversion kernel (one launch, all tensors) -----------
#define CV_NX ((N_TOK * C_DIM) / 4)     // 8388608
#define CV_NW ((C_DIM * HS) / 4)        // 524288
#define CV_NE ((NE * C_DIM * HR) / 4)   // 2097152
#define CV_TOTAL (CV_NX + 3 * CV_NW + 2 * CV_NE)   // 14155776

__global__ void k_convall(
    const float* __restrict__ x,
    const float* __restrict__ sw1, const float* __restrict__ sw3,
    const float* __restrict__ sw2,
    const float* __restrict__ w1,  const float* __restrict__ w2)
{
    int i = blockIdx.x * blockDim.x + threadIdx.x;
    if (i >= CV_TOTAL) return;
    if (i < CV_NX) {
        // x with residue-major row permutation
        int t = i >> 8;                  // 256 float4 per row
        int c = i & 255;
        int pr = ((t & 7) << 12) | (t >> 3);
        float4 v = ((const float4*)x)[i];
        __half2* d = (__half2*)g_xh + (size_t)pr * (C_DIM / 2) + c * 2;
        d[0] = __floats2half2_rn(v.x, v.y);
        d[1] = __floats2half2_rn(v.z, v.w);
        return;
    }
    i -= CV_NX;
    const float* src; __half2* d; float sc;
    if (i < CV_NW)               { src = sw1; d = (__half2*)g_sw1h; sc = 1.0f; }
    else if (i < 2 * CV_NW)      { src = sw3; d = (__half2*)g_sw3h; sc = 1.0f; i -= CV_NW; }
    else if (i < 3 * CV_NW)      { src = sw2; d = (__half2*)g_sw2h; sc = 0.5f; i -= 2 * CV_NW; }
    else if (i < 3 * CV_NW + CV_NE) { src = w1; d = (__half2*)g_w1h; sc = 1.0f; i -= 3 * CV_NW; }
    else                         { src = w2; d = (__half2*)g_w2h; sc = 0.25f; i -= 3 * CV_NW + CV_NE; }
    float4 v = ((const float4*)src)[i];
    d[2 * i]     = __floats2half2_rn(v.x * sc, v.y * sc);
    d[2 * i + 1] = __floats2half2_rn(v.z * sc, v.w * sc);
}

// combined down bias: g_biasD[rr][col] = 0.5*sb2 + 0.25*(b2[e0]+b2[e1])
__global__ void k_bias(const float* __restrict__ sb2, const float* __restrict__ b2) {
    int i = blockIdx.x * blockDim.x + threadIdx.x;
    if (i >= NE * C_DIM) return;
    int rr = i >> 10, col = i & 1023;
    int e0 = (3 * rr) & 7;
    int e1 = (3 * rr + 7) & 7;
    g_biasD[i] = 0.5f * sb2[col]
               + 0.25f * (b2[e0 * C_DIM + col] + b2[e1 * C_DIM + col]);
}

// ---------------- generic stage fill (BK=64, cp.async) ----------------
__device__ __forceinline__ void fill_stage(
    const __half* __restrict__ A, int strideA,
    const __half* __restrict__ B, int ldb,
    int m0, int n0, int kt, __half* Asb, __half* Bsb, int tid)
{
#pragma unroll
    for (int i = 0; i < 4; i++) {              // A: 128x64 halfs = 1024 x 16B chunks
        int c = tid + i * 256;
        int ar = c >> 3, ac = c & 7;
        cp16(Asb + ar * ASTR + ac * 8,
             A + (size_t)(m0 + ar) * strideA + kt * BK + ac * 8);
    }
#pragma unroll
    for (int i = 0; i < 4; i++) {              // B: 64x128 halfs = 1024 x 16B chunks
        int c = tid + i * 256;
        int br = c >> 4, bc = c & 15;
        cp16(Bsb + br * BSTR + bc * 8,
             B + (size_t)(kt * BK + br) * ldb + n0 + bc * 8);
    }
}

// ---------------- warp-tile compute on one resident stage (128x128, BK=64) ----------
__device__ __forceinline__ void compute_stage(
    const __half* As, const __half* Bs, float acc[2][8][4],
    int wm, int wn, int lane)
{
#pragma unroll
    for (int ks = 0; ks < 4; ks++) {           // four k16 steps per BK=64
        uint32_t a[2][4];
#pragma unroll
        for (int mi = 0; mi < 2; mi++) {
            const __half* p = &As[(wm * 32 + mi * 16 + (lane & 15)) * ASTR
                                  + ks * 16 + (lane >> 4) * 8];
            ldsm4(a[mi], p);
        }
#pragma unroll
        for (int p4 = 0; p4 < 4; p4++) {       // 16 cols per ldmatrix.x4.trans
            uint32_t b[4];
            const __half* p = &Bs[(ks * 16 + (lane & 7) + ((lane >> 3) & 1) * 8) * BSTR
                                  + wn * 64 + p4 * 16 + (lane >> 4) * 8];
            ldsm4t(b, p);
            mma16816(acc[0][2 * p4 + 0], a[0], &b[0]);
            mma16816(acc[0][2 * p4 + 1], a[0], &b[2]);
            mma16816(acc[1][2 * p4 + 0], a[1], &b[0]);
            mma16816(acc[1][2 * p4 + 1], a[1], &b[2]);
        }
    }
}

// ---------------- up-fused stage fill: A=x(perm), B=[sw1 64cols | sw3 64cols] -----
__device__ __forceinline__ void fill_stage_up(
    int kt, int m0, int n0, __half* Asb, __half* Bsb, int tid)
{
#pragma unroll
    for (int i = 0; i < 4; i++) {              // A: 128x64 halfs
        int c = tid + i * 256;
        int ar = c >> 3, ac = c & 7;
        cp16(Asb + ar * ASTR + ac * 8,
             g_xh + (size_t)(m0 + ar) * C_DIM + kt * BK + ac * 8);
    }
#pragma unroll
    for (int i = 0; i < 4; i++) {              // B: 64 rows x (64|64) halfs
        int c = tid + i * 256;
        int br = c >> 4, bc = c & 15;
        if (bc < 8)
            cp16(Bsb + br * BSTR + bc * 8,
                 g_sw1h + (size_t)(kt * BK + br) * HS + n0 + bc * 8);
        else
            cp16(Bsb + br * BSTR + 64 + (bc - 8) * 8,
                 g_sw3h + (size_t)(kt * BK + br) * HS + n0 + (bc - 8) * 8);
    }
}

// ================= merged UP kernel ==========================================
// 1D grid, 12288 CTAs:
//   bid < 8192 : shared-up tile (128 permuted rows x 64 H2-cols, both branches)
//   bid >= 8192: routed-up tile (128x128, gelu)
__global__ __launch_bounds__(256, 2) void k_up_all(
    const float* __restrict__ sb1, const float* __restrict__ sb3,
    const float* __restrict__ b1)
{
    extern __shared__ __align__(16) __half smem[];
    __half* Asm = smem;
    __half* Bsm = smem + NSTG * A_ST;

    const int tid = threadIdx.x;
    const int bid = blockIdx.x;
    const int warp = tid >> 5, lane = tid & 31;
    const int KT = C_DIM / BK;                 // 16

    if (bid < 8192) {
        // ---------- shared up: H2 = silu(x@sw1+b1)*(x@sw3+b3) ----------
        const int m0 = (bid >> 5) * BM;
        const int n0 = (bid & 31) * 64;
        const int wm = warp & 3, wn = (warp >> 2) & 1;

#pragma unroll
        for (int c = 0; c < NSTG - 1; c++) {
            fill_stage_up(c, m0, n0, Asm + c * A_ST, Bsm + c * B_ST, tid);
            asm volatile("cp.async.commit_group;");
        }

        float acc1[2][4][4], acc3[2][4][4];
#pragma unroll
        for (int i = 0; i < 2; i++)
#pragma unroll
            for (int j = 0; j < 4; j++)
#pragma unroll
                for (int e = 0; e < 4; e++) { acc1[i][j][e] = 0.f; acc3[i][j][e] = 0.f; }

        int s = 0, fs = NSTG - 1;
        for (int kt = 0; kt < KT; ++kt) {
            asm volatile("cp.async.wait_group %0;" :: "n"(NSTG - 2));
            __syncthreads();

            const __half* As = Asm + s * A_ST;
            const __half* Bs = Bsm + s * B_ST;
#pragma unroll
            for (int ks = 0; ks < 4; ks++) {
                uint32_t a[2][4];
#pragma unroll
                for (int mi = 0; mi < 2; mi++) {
                    const __half* p = &As[(wm * 32 + mi * 16 + (lane & 15)) * ASTR
                                          + ks * 16 + (lane >> 4) * 8];
                    ldsm4(a[mi], p);
                }
                const int brow = (ks * 16 + (lane & 7) + ((lane >> 3) & 1) * 8) * BSTR
                                 + (lane >> 4) * 8;
#pragma unroll
                for (int p4 = 0; p4 < 2; p4++) {   // branch 1 (sw1)
                    uint32_t b[4];
                    ldsm4t(b, &Bs[brow + wn * 32 + p4 * 16]);
                    mma16816(acc1[0][2 * p4 + 0], a[0], &b[0]);
                    mma16816(acc1[0][2 * p4 + 1], a[0], &b[2]);
                    mma16816(acc1[1][2 * p4 + 0], a[1], &b[0]);
                    mma16816(acc1[1][2 * p4 + 1], a[1], &b[2]);
                }
#pragma unroll
                for (int p4 = 0; p4 < 2; p4++) {   // branch 3 (sw3): +64 col offset
                    uint32_t b[4];
                    ldsm4t(b, &Bs[brow + 64 + wn * 32 + p4 * 16]);
                    mma16816(acc3[0][2 * p4 + 0], a[0], &b[0]);
                    mma16816(acc3[0][2 * p4 + 1], a[0], &b[2]);
                    mma16816(acc3[1][2 * p4 + 0], a[1], &b[0]);
                    mma16816(acc3[1][2 * p4 + 1], a[1], &b[2]);
                }
            }

            // refill the slot released at this iteration's sync (compute first!)
            if (kt + NSTG - 1 < KT)
                fill_stage_up(kt + NSTG - 1, m0, n0,
                              Asm + fs * A_ST, Bsm + fs * B_ST, tid);
            asm volatile("cp.async.commit_group;");

            if (++s == NSTG) s = 0;
            if (++fs == NSTG) fs = 0;
        }

#pragma unroll
        for (int mi = 0; mi < 2; mi++)
#pragma unroll
            for (int ni = 0; ni < 4; ni++)
#pragma unroll
                for (int pp = 0; pp < 2; pp++) {
                    int row = m0 + wm * 32 + mi * 16 + (lane >> 2) + pp * 8;
                    int col = n0 + wn * 32 + ni * 8 + (lane & 3) * 2;
                    float u0 = acc1[mi][ni][2 * pp + 0] + sb1[col];
                    float u1 = acc1[mi][ni][2 * pp + 1] + sb1[col + 1];
                    float w0 = acc3[mi][ni][2 * pp + 0] + sb3[col];
                    float w1 = acc3[mi][ni][2 * pp + 1] + sb3[col + 1];
                    float v0 = u0 / (1.f + __expf(-u0)) * w0;
                    float v1 = u1 / (1.f + __expf(-u1)) * w1;
                    *(__half2*)(g_H2 + (size_t)row * HS + col) = __floats2half2_rn(v0, v1);
                }
    } else {
        // ---------- routed up: Hr[z] = gelu(x_perm[rr block] @ w1[e] + b1[e]) ------
        const int rid = bid - 8192;
        const int z = rid >> 8;               // 0..15, z = kk*8 + rr
        const int rr = z & 7, kk = z >> 3;
        const int e = (3 * rr + 7 * kk) & 7;
        const int m0 = ((rid >> 3) & 31) * BM;
        const int n0 = (rid & 7) * BN;
        const __half* A = g_xh + (size_t)rr * 4096 * C_DIM;   // contiguous rows
        const __half* B = g_w1h + (size_t)e * C_DIM * HR;
        __half* outp = g_Hr + (size_t)z * 4096 * HR;
        const float* bias = b1 + e * HR;
        const int wm = warp & 3, wn = warp >> 2;

#pragma unroll
        for (int c = 0; c < NSTG - 1; c++) {
            fill_stage(A, C_DIM, B, HR, m0, n0, c,
                       Asm + c * A_ST, Bsm + c * B_ST, tid);
            asm volatile("cp.async.commit_group;");
        }

        float acc[2][8][4];
#pragma unroll
        for (int i = 0; i < 2; i++)
#pragma unroll
            for (int j = 0; j < 8; j++)
#pragma unroll
                for (int ee = 0; ee < 4; ee++) acc[i][j][ee] = 0.f;

        int s = 0, fs = NSTG - 1;
        for (int kt = 0; kt < KT; ++kt) {
            asm volatile("cp.async.wait_group %0;" :: "n"(NSTG - 2));
            __syncthreads();

            compute_stage(Asm + s * A_ST, Bsm + s * B_ST, acc, wm, wn, lane);

            if (kt + NSTG - 1 < KT)
                fill_stage(A, C_DIM, B, HR, m0, n0, kt + NSTG - 1,
                           Asm + fs * A_ST, Bsm + fs * B_ST, tid);
            asm volatile("cp.async.commit_group;");

            if (++s == NSTG) s = 0;
            if (++fs == NSTG) fs = 0;
        }

#pragma unroll
        for (int mi = 0; mi < 2; mi++)
#pragma unroll
            for (int ni = 0; ni < 8; ni++)
#pragma unroll
                for (int pp = 0; pp < 2; pp++) {
                    int row = m0 + wm * 32 + mi * 16 + (lane >> 2) + pp * 8;
                    int col = n0 + wn * 64 + ni * 8 + (lane & 3) * 2;
                    float v0 = acc[mi][ni][2 * pp + 0] + bias[col];
                    float v1 = acc[mi][ni][2 * pp + 1] + bias[col + 1];
                    v0 = 0.5f * v0 * (1.f + erff(v0 * 0.70710678118654752f));
                    v1 = 0.5f * v1 * (1.f + erff(v1 * 0.70710678118654752f));
                    *(__half2*)(outp + (size_t)row * HR + col) = __floats2half2_rn(v0, v1);
                }
    }
}

// ---------------- mega down kernel: out = 0.5*shared_down + 0.25*(y0+y1) ------
// Three K-segments (BK=64), all contiguous A in permuted space:
//   kt [0,32):  H2_perm[rr block] @ (0.5*sw2)
//   kt [32,48): Hr[rr]   @ (0.25*w2[e0])
//   kt [48,64): Hr[8+rr] @ (0.25*w2[e1])
#define KT_MEGA 64
__device__ __forceinline__ void mega_map(int kt, int rr, int e0, int e1,
                                         const __half*& Ap, int& sA, const __half*& Bp) {
    if (kt < 32) {
        Ap = g_H2 + (size_t)rr * 4096 * HS + (size_t)kt * BK;
        sA = HS;
        Bp = g_sw2h + (size_t)kt * BK * C_DIM;
    } else if (kt < 48) {
        Ap = g_Hr + (size_t)rr * 4096 * HR + (size_t)(kt - 32) * BK;
        sA = HR;
        Bp = g_w2h + (size_t)e0 * HR * C_DIM + (size_t)(kt - 32) * BK * C_DIM;
    } else {
        Ap = g_Hr + (size_t)(8 + rr) * 4096 * HR + (size_t)(kt - 48) * BK;
        sA = HR;
        Bp = g_w2h + (size_t)e1 * HR * C_DIM + (size_t)(kt - 48) * BK * C_DIM;
    }
}
__device__ __forceinline__ void fill_stage_mega(
    int kt, int rr, int e0, int e1, int m0, int n0,
    __half* Asb, __half* Bsb, int tid)
{
    const __half* Ap; const __half* Bp; int sA;
    mega_map(kt, rr, e0, e1, Ap, sA, Bp);
#pragma unroll
    for (int i = 0; i < 4; i++) {
        int c = tid + i * 256;
        int ar = c >> 3, ac = c & 7;
        cp16(Asb + ar * ASTR + ac * 8,
             Ap + (size_t)(m0 + ar) * sA + ac * 8);
    }
#pragma unroll
    for (int i = 0; i < 4; i++) {
        int c = tid + i * 256;
        int br = c >> 4, bc = c & 15;
        cp16(Bsb + br * BSTR + bc * 8,
             Bp + (size_t)br * C_DIM + n0 + bc * 8);
    }
}
__global__ __launch_bounds__(256, 2) void k_down_mega(float* __restrict__ dout)
{
    extern __shared__ __align__(16) __half smem[];
    __half* Asm = smem;
    __half* Bsm = smem + NSTG * A_ST;

    const int rr = blockIdx.z;
    const int e0 = (3 * rr) & 7;
    const int e1 = (3 * rr + 7) & 7;
    const int tid = threadIdx.x;
    const int m0 = blockIdx.y * BM;
    const int n0 = blockIdx.x * BN;

#pragma unroll
    for (int c = 0; c < NSTG - 1; c++) {
        fill_stage_mega(c, rr, e0, e1, m0, n0,
                        Asm + c * A_ST, Bsm + c * B_ST, tid);
        asm volatile("cp.async.commit_group;");
    }

    float acc[2][8][4];
#pragma unroll
    for (int i = 0; i < 2; i++)
#pragma unroll
        for (int j = 0; j < 8; j++)
#pragma unroll
            for (int e = 0; e < 4; e++) acc[i][j][e] = 0.f;

    const int warp = tid >> 5, lane = tid & 31;
    const int wm = warp & 3, wn = warp >> 2;

    int s = 0, fs = NSTG - 1;
    for (int kt = 0; kt < KT_MEGA; ++kt) {
        asm volatile("cp.async.wait_group %0;" :: "n"(NSTG - 2));
        __syncthreads();

        compute_stage(Asm + s * A_ST, Bsm + s * B_ST, acc, wm, wn, lane);

        if (kt + NSTG - 1 < KT_MEGA)
            fill_stage_mega(kt + NSTG - 1, rr, e0, e1, m0, n0,
                            Asm + fs * A_ST, Bsm + fs * B_ST, tid);
        asm volatile("cp.async.commit_group;");

        if (++s == NSTG) s = 0;
        if (++fs == NSTG) fs = 0;
    }

    // epilogue: single fp32 write, precomputed combined bias, un-permute rows
    const float* biasD = g_biasD + rr * C_DIM;
#pragma unroll
    for (int mi = 0; mi < 2; mi++)
#pragma unroll
        for (int ni = 0; ni < 8; ni++)
#pragma unroll
            for (int pp = 0; pp < 2; pp++) {
                int rowl = m0 + wm * 32 + mi * 16 + (lane >> 2) + pp * 8;
                int col  = n0 + wn * 64 + ni * 8 + (lane & 3) * 2;
                float2 bb = *(const float2*)(biasD + col);
                float2 f;
                f.x = acc[mi][ni][2 * pp + 0] + bb.x;
                f.y = acc[mi][ni][2 * pp + 1] + bb.y;
                size_t t = (size_t)rr + 8 * (size_t)rowl;    // actual token
                *(float2*)(dout + t * C_DIM + col) = f;
            }
}

// ---------------- launch ----------------
extern "C" void kernel_launch(void* const* d_in, const int* in_sizes, int n_in,
                              void* d_out, int out_size) {
    const float* x   = (const float*)d_in[0];
    // d_in[1] = t_emb : unused by reference
    const float* sw1 = (const float*)d_in[2];
    const float* sb1 = (const float*)d_in[3];
    const float* sw3 = (const float*)d_in[4];
    const float* sb3 = (const float*)d_in[5];
    const float* sw2 = (const float*)d_in[6];
    const float* sb2 = (const float*)d_in[7];
    const float* w1  = (const float*)d_in[8];
    const float* b1  = (const float*)d_in[9];
    const float* w2  = (const float*)d_in[10];
    const float* b2  = (const float*)d_in[11];
    float* out = (float*)d_out;

    cudaFuncSetAttribute(k_up_all,    cudaFuncAttributeMaxDynamicSharedMemorySize, SMEM_BYTES);
    cudaFuncSetAttribute(k_down_mega, cudaFuncAttributeMaxDynamicSharedMemorySize, SMEM_BYTES);

    // one merged conversion launch + tiny bias kernel
    k_convall<<<(CV_TOTAL + 255) / 256, 256>>>(x, sw1, sw3, sw2, w1, w2);
    k_bias<<<(NE * C_DIM + 255) / 256, 256>>>(sb2, b2);

    // merged up path: shared SwiGLU (8192 CTAs) + routed gelu (4096 CTAs)
    k_up_all<<<12288, 256, SMEM_BYTES>>>(sb1, sb3, b1);

    // fused down path: single pass, single out write
    k_down_mega<<<dim3(C_DIM / BN, 4096 / BM, 8), 256, SMEM_BYTES>>>(out);
}

// round 15
// speedup vs baseline: 1.0974x; 1.0007x over previous
#include <cuda_runtime.h>
#include <cuda_fp16.h>
#include <stdint.h>
#include <math.h>

// ---------------- problem constants ----------------
#define N_TOK 32768      // B*T = 4*8192
#define C_DIM 1024
#define HS    2048
#define HR    1024
#define NE    8

// Token permutation: physical row = (t & 7) * 4096 + (t >> 3)  (residue-major).

// ---------------- GEMM tile config (validated optimum) ----------------
#define BM 128
#define BN 128
#define BK 64
#define NSTG 3
#define ASTR (BK + 8)    // 72 halfs/row (144B, conflict-free ldmatrix)
#define BSTR (BN + 8)    // 136 halfs/row (272B, conflict-free ldmatrix.trans)
#define A_ST (BM * ASTR)             // 9216 halfs per A stage
#define B_ST (BK * BSTR)             // 8704 halfs per B stage
#define SMEM_BYTES (NSTG * (A_ST + B_ST) * 2)   // 107520 B -> 2 CTAs/SM

// ---------------- static scratch (no allocations allowed) ----------------
__device__ __half g_xh[N_TOK * C_DIM];          // x fp16, residue-major permuted
__device__ __half g_sw1h[C_DIM * HS];
__device__ __half g_sw3h[C_DIM * HS];
__device__ __half g_sw2h[HS * C_DIM];           // pre-scaled by 0.5
__device__ __half g_w1h[NE * C_DIM * HR];
__device__ __half g_w2h[NE * HR * C_DIM];       // pre-scaled by 0.25
__device__ __half g_H2[N_TOK * HS];             // swiglu hidden, permuted rows
__device__ __half g_Hr[2 * N_TOK * HR];         // routed hidden [k*8+r][4096][HR]
__device__ float  g_biasD[NE * C_DIM];          // combined down bias per residue

// ---------------- small PTX helpers ----------------
__device__ __forceinline__ void cp16(void* s, const void* g) {
    unsigned sa = (unsigned)__cvta_generic_to_shared(s);
    asm volatile("cp.async.cg.shared.global [%0], [%1], 16;" :: "r"(sa), "l"(g));
}
__device__ __forceinline__ void ldsm4(uint32_t* r, const __half* p) {
    unsigned a = (unsigned)__cvta_generic_to_shared(p);
    asm volatile("ldmatrix.sync.aligned.m8n8.x4.shared.b16 {%0,%1,%2,%3}, [%4];"
                 : "=r"(r[0]), "=r"(r[1]), "=r"(r[2]), "=r"(r[3]) : "r"(a));
}
__device__ __forceinline__ void ldsm4t(uint32_t* r, const __half* p) {
    unsigned a = (unsigned)__cvta_generic_to_shared(p);
    asm volatile("ldmatrix.sync.aligned.m8n8.x4.trans.shared.b16 {%0,%1,%2,%3}, [%4];"
                 : "=r"(r[0]), "=r"(r[1]), "=r"(r[2]), "=r"(r[3]) : "r"(a));
}
__device__ __forceinline__ void mma16816(float* d, const uint32_t* a, const uint32_t* b) {
    asm volatile(
        "mma.sync.aligned.m16n8k16.row.col.f32.f16.f16.f32 "
        "{%0,%1,%2,%3},{%4,%5,%6,%7},{%8,%9},{%0,%1,%2,%3};"
        : "+f"(d[0]), "+f"(d[1]), "+f"(d[2]), "+f"(d[3])
        : "r"(a[0]), "r"(a[1]), "r"(a[2]), "r"(a[3]), "r"(b[0]), "r"(b[1]));
}

// Anti-phase stagger: co-resident CTA pairs are (bid, bid+148) in wave 1 and
// inherit phase afterwards. Delaying the second set ~half a k-iteration breaks
// the barrier phase-lock so the two CTAs' compute/barrier windows interleave.
__device__ __forceinline__ void stagger(unsigned linbid) {
    if ((linbid / 148u) & 1u) __nanosleep(400);
}

// ---------------- merged conversion kernel (one launch, MLP x4) -----------
#define CV_NX ((N_TOK * C_DIM) / 4)     // 8388608
#define CV_NW ((C_DIM * HS) / 4)        // 524288
#define CV_NE ((NE * C_DIM * HR) / 4)   // 2097152
#define CV_TOTAL (CV_NX + 3 * CV_NW + 2 * CV_NE)   // 14155776
#define CV_QUARTER (CV_TOTAL / 4)                   // 3538944 (multiple of 256)

__device__ __forceinline__ void conv_one(
    int i,
    const float* __restrict__ x,
    const float* __restrict__ sw1, const float* __restrict__ sw3,
    const float* __restrict__ sw2,
    const float* __restrict__ w1,  const float* __restrict__ w2)
{
    if (i < CV_NX) {
        int t = i >> 8;                  // 256 float4 per row
        int c = i & 255;
        int pr = ((t & 7) << 12) | (t >> 3);
        float4 v = ((const float4*)x)[i];
        __half2* d = (__half2*)g_xh + (size_t)pr * (C_DIM / 2) + c * 2;
        d[0] = __floats2half2_rn(v.x, v.y);
        d[1] = __floats2half2_rn(v.z, v.w);
        return;
    }
    i -= CV_NX;
    const float* src; __half2* d; float sc;
    if (i < CV_NW)                  { src = sw1; d = (__half2*)g_sw1h; sc = 1.0f; }
    else if (i < 2 * CV_NW)         { src = sw3; d = (__half2*)g_sw3h; sc = 1.0f; i -= CV_NW; }
    else if (i < 3 * CV_NW)         { src = sw2; d = (__half2*)g_sw2h; sc = 0.5f; i -= 2 * CV_NW; }
    else if (i < 3 * CV_NW + CV_NE) { src = w1;  d = (__half2*)g_w1h;  sc = 1.0f; i -= 3 * CV_NW; }
    else                            { src = w2;  d = (__half2*)g_w2h;  sc = 0.25f; i -= 3 * CV_NW + CV_NE; }
    float4 v = ((const float4*)src)[i];
    d[2 * i]     = __floats2half2_rn(v.x * sc, v.y * sc);
    d[2 * i + 1] = __floats2half2_rn(v.z * sc, v.w * sc);
}

__global__ void k_convall(
    const float* __restrict__ x,
    const float* __restrict__ sw1, const float* __restrict__ sw3,
    const float* __restrict__ sw2,
    const float* __restrict__ w1,  const float* __restrict__ w2)
{
    int base = blockIdx.x * blockDim.x + threadIdx.x;   // [0, CV_QUARTER)
#pragma unroll
    for (int u = 0; u < 4; u++)
        conv_one(base + u * CV_QUARTER, x, sw1, sw3, sw2, w1, w2);
}

// combined down bias: g_biasD[rr][col] = 0.5*sb2 + 0.25*(b2[e0]+b2[e1])
__global__ void k_bias(const float* __restrict__ sb2, const float* __restrict__ b2) {
    int i = blockIdx.x * blockDim.x + threadIdx.x;
    if (i >= NE * C_DIM) return;
    int rr = i >> 10, col = i & 1023;
    int e0 = (3 * rr) & 7;
    int e1 = (3 * rr + 7) & 7;
    g_biasD[i] = 0.5f * sb2[col]
               + 0.25f * (b2[e0 * C_DIM + col] + b2[e1 * C_DIM + col]);
}

// ---------------- generic stage fill (BK=64, cp.async) ----------------
__device__ __forceinline__ void fill_stage(
    const __half* __restrict__ A, int strideA,
    const __half* __restrict__ B, int ldb,
    int m0, int n0, int kt, __half* Asb, __half* Bsb, int tid)
{
#pragma unroll
    for (int i = 0; i < 4; i++) {              // A: 128x64 halfs = 1024 x 16B chunks
        int c = tid + i * 256;
        int ar = c >> 3, ac = c & 7;
        cp16(Asb + ar * ASTR + ac * 8,
             A + (size_t)(m0 + ar) * strideA + kt * BK + ac * 8);
    }
#pragma unroll
    for (int i = 0; i < 4; i++) {              // B: 64x128 halfs = 1024 x 16B chunks
        int c = tid + i * 256;
        int br = c >> 4, bc = c & 15;
        cp16(Bsb + br * BSTR + bc * 8,
             B + (size_t)(kt * BK + br) * ldb + n0 + bc * 8);
    }
}

// ---------------- warp-tile compute on one resident stage (128x128, BK=64) ----------
__device__ __forceinline__ void compute_stage(
    const __half* As, const __half* Bs, float acc[2][8][4],
    int wm, int wn, int lane)
{
#pragma unroll
    for (int ks = 0; ks < 4; ks++) {           // four k16 steps per BK=64
        uint32_t a[2][4];
#pragma unroll
        for (int mi = 0; mi < 2; mi++) {
            const __half* p = &As[(wm * 32 + mi * 16 + (lane & 15)) * ASTR
                                  + ks * 16 + (lane >> 4) * 8];
            ldsm4(a[mi], p);
        }
#pragma unroll
        for (int p4 = 0; p4 < 4; p4++) {       // 16 cols per ldmatrix.x4.trans
            uint32_t b[4];
            const __half* p = &Bs[(ks * 16 + (lane & 7) + ((lane >> 3) & 1) * 8) * BSTR
                                  + wn * 64 + p4 * 16 + (lane >> 4) * 8];
            ldsm4t(b, p);
            mma16816(acc[0][2 * p4 + 0], a[0], &b[0]);
            mma16816(acc[0][2 * p4 + 1], a[0], &b[2]);
            mma16816(acc[1][2 * p4 + 0], a[1], &b[0]);
            mma16816(acc[1][2 * p4 + 1], a[1], &b[2]);
        }
    }
}

// ---------------- up-fused stage fill: A=x(perm), B=[sw1 64cols | sw3 64cols] -----
__device__ __forceinline__ void fill_stage_up(
    int kt, int m0, int n0, __half* Asb, __half* Bsb, int tid)
{
#pragma unroll
    for (int i = 0; i < 4; i++) {              // A: 128x64 halfs
        int c = tid + i * 256;
        int ar = c >> 3, ac = c & 7;
        cp16(Asb + ar * ASTR + ac * 8,
             g_xh + (size_t)(m0 + ar) * C_DIM + kt * BK + ac * 8);
    }
#pragma unroll
    for (int i = 0; i < 4; i++) {              // B: 64 rows x (64|64) halfs
        int c = tid + i * 256;
        int br = c >> 4, bc = c & 15;
        if (bc < 8)
            cp16(Bsb + br * BSTR + bc * 8,
                 g_sw1h + (size_t)(kt * BK + br) * HS + n0 + bc * 8);
        else
            cp16(Bsb + br * BSTR + 64 + (bc - 8) * 8,
                 g_sw3h + (size_t)(kt * BK + br) * HS + n0 + (bc - 8) * 8);
    }
}

// ================= merged UP kernel ==========================================
// 1D grid, 12288 CTAs:
//   bid < 8192 : shared-up tile (128 permuted rows x 64 H2-cols, both branches)
//   bid >= 8192: routed-up tile (128x128, gelu)
__global__ __launch_bounds__(256, 2) void k_up_all(
    const float* __restrict__ sb1, const float* __restrict__ sb3,
    const float* __restrict__ b1)
{
    extern __shared__ __align__(16) __half smem[];
    __half* Asm = smem;
    __half* Bsm = smem + NSTG * A_ST;

    const int tid = threadIdx.x;
    const int bid = blockIdx.x;
    const int warp = tid >> 5, lane = tid & 31;
    const int KT = C_DIM / BK;                 // 16

    stagger((unsigned)bid);

    if (bid < 8192) {
        // ---------- shared up: H2 = silu(x@sw1+b1)*(x@sw3+b3) ----------
        const int m0 = (bid >> 5) * BM;
        const int n0 = (bid & 31) * 64;
        const int wm = warp & 3, wn = (warp >> 2) & 1;

#pragma unroll
        for (int c = 0; c < NSTG - 1; c++) {
            fill_stage_up(c, m0, n0, Asm + c * A_ST, Bsm + c * B_ST, tid);
            asm volatile("cp.async.commit_group;");
        }

        float acc1[2][4][4], acc3[2][4][4];
#pragma unroll
        for (int i = 0; i < 2; i++)
#pragma unroll
            for (int j = 0; j < 4; j++)
#pragma unroll
                for (int e = 0; e < 4; e++) { acc1[i][j][e] = 0.f; acc3[i][j][e] = 0.f; }

        int s = 0, fs = NSTG - 1;
        for (int kt = 0; kt < KT; ++kt) {
            asm volatile("cp.async.wait_group %0;" :: "n"(NSTG - 2));
            __syncthreads();

            const __half* As = Asm + s * A_ST;
            const __half* Bs = Bsm + s * B_ST;
#pragma unroll
            for (int ks = 0; ks < 4; ks++) {
                uint32_t a[2][4];
#pragma unroll
                for (int mi = 0; mi < 2; mi++) {
                    const __half* p = &As[(wm * 32 + mi * 16 + (lane & 15)) * ASTR
                                          + ks * 16 + (lane >> 4) * 8];
                    ldsm4(a[mi], p);
                }
                const int brow = (ks * 16 + (lane & 7) + ((lane >> 3) & 1) * 8) * BSTR
                                 + (lane >> 4) * 8;
#pragma unroll
                for (int p4 = 0; p4 < 2; p4++) {   // branch 1 (sw1)
                    uint32_t b[4];
                    ldsm4t(b, &Bs[brow + wn * 32 + p4 * 16]);
                    mma16816(acc1[0][2 * p4 + 0], a[0], &b[0]);
                    mma16816(acc1[0][2 * p4 + 1], a[0], &b[2]);
                    mma16816(acc1[1][2 * p4 + 0], a[1], &b[0]);
                    mma16816(acc1[1][2 * p4 + 1], a[1], &b[2]);
                }
#pragma unroll
                for (int p4 = 0; p4 < 2; p4++) {   // branch 3 (sw3): +64 col offset
                    uint32_t b[4];
                    ldsm4t(b, &Bs[brow + 64 + wn * 32 + p4 * 16]);
                    mma16816(acc3[0][2 * p4 + 0], a[0], &b[0]);
                    mma16816(acc3[0][2 * p4 + 1], a[0], &b[2]);
                    mma16816(acc3[1][2 * p4 + 0], a[1], &b[0]);
                    mma16816(acc3[1][2 * p4 + 1], a[1], &b[2]);
                }
            }

            // refill the slot released at this iteration's sync (compute first!)
            if (kt + NSTG - 1 < KT)
                fill_stage_up(kt + NSTG - 1, m0, n0,
                              Asm + fs * A_ST, Bsm + fs * B_ST, tid);
            asm volatile("cp.async.commit_group;");

            if (++s == NSTG) s = 0;
            if (++fs == NSTG) fs = 0;
        }

#pragma unroll
        for (int mi = 0; mi < 2; mi++)
#pragma unroll
            for (int ni = 0; ni < 4; ni++)
#pragma unroll
                for (int pp = 0; pp < 2; pp++) {
                    int row = m0 + wm * 32 + mi * 16 + (lane >> 2) + pp * 8;
                    int col = n0 + wn * 32 + ni * 8 + (lane & 3) * 2;
                    float u0 = acc1[mi][ni][2 * pp + 0] + sb1[col];
                    float u1 = acc1[mi][ni][2 * pp + 1] + sb1[col + 1];
                    float w0 = acc3[mi][ni][2 * pp + 0] + sb3[col];
                    float w1 = acc3[mi][ni][2 * pp + 1] + sb3[col + 1];
                    float v0 = u0 / (1.f + __expf(-u0)) * w0;
                    float v1 = u1 / (1.f + __expf(-u1)) * w1;
                    *(__half2*)(g_H2 + (size_t)row * HS + col) = __floats2half2_rn(v0, v1);
                }
    } else {
        // ---------- routed up: Hr[z] = gelu(x_perm[rr block] @ w1[e] + b1[e]) ------
        const int rid = bid - 8192;
        const int z = rid >> 8;               // 0..15, z = kk*8 + rr
        const int rr = z & 7, kk = z >> 3;
        const int e = (3 * rr + 7 * kk) & 7;
        const int m0 = ((rid >> 3) & 31) * BM;
        const int n0 = (rid & 7) * BN;
        const __half* A = g_xh + (size_t)rr * 4096 * C_DIM;   // contiguous rows
        const __half* B = g_w1h + (size_t)e * C_DIM * HR;
        __half* outp = g_Hr + (size_t)z * 4096 * HR;
        const float* bias = b1 + e * HR;
        const int wm = warp & 3, wn = warp >> 2;

#pragma unroll
        for (int c = 0; c < NSTG - 1; c++) {
            fill_stage(A, C_DIM, B, HR, m0, n0, c,
                       Asm + c * A_ST, Bsm + c * B_ST, tid);
            asm volatile("cp.async.commit_group;");
        }

        float acc[2][8][4];
#pragma unroll
        for (int i = 0; i < 2; i++)
#pragma unroll
            for (int j = 0; j < 8; j++)
#pragma unroll
                for (int ee = 0; ee < 4; ee++) acc[i][j][ee] = 0.f;

        int s = 0, fs = NSTG - 1;
        for (int kt = 0; kt < KT; ++kt) {
            asm volatile("cp.async.wait_group %0;" :: "n"(NSTG - 2));
            __syncthreads();

            compute_stage(Asm + s * A_ST, Bsm + s * B_ST, acc, wm, wn, lane);

            if (kt + NSTG - 1 < KT)
                fill_stage(A, C_DIM, B, HR, m0, n0, kt + NSTG - 1,
                           Asm + fs * A_ST, Bsm + fs * B_ST, tid);
            asm volatile("cp.async.commit_group;");

            if (++s == NSTG) s = 0;
            if (++fs == NSTG) fs = 0;
        }

#pragma unroll
        for (int mi = 0; mi < 2; mi++)
#pragma unroll
            for (int ni = 0; ni < 8; ni++)
#pragma unroll
                for (int pp = 0; pp < 2; pp++) {
                    int row = m0 + wm * 32 + mi * 16 + (lane >> 2) + pp * 8;
                    int col = n0 + wn * 64 + ni * 8 + (lane & 3) * 2;
                    float v0 = acc[mi][ni][2 * pp + 0] + bias[col];
                    float v1 = acc[mi][ni][2 * pp + 1] + bias[col + 1];
                    v0 = 0.5f * v0 * (1.f + erff(v0 * 0.70710678118654752f));
                    v1 = 0.5f * v1 * (1.f + erff(v1 * 0.70710678118654752f));
                    *(__half2*)(outp + (size_t)row * HR + col) = __floats2half2_rn(v0, v1);
                }
    }
}

// ---------------- mega down kernel: out = 0.5*shared_down + 0.25*(y0+y1) ------
// Three K-segments (BK=64), all contiguous A in permuted space:
//   kt [0,32):  H2_perm[rr block] @ (0.5*sw2)
//   kt [32,48): Hr[rr]   @ (0.25*w2[e0])
//   kt [48,64): Hr[8+rr] @ (0.25*w2[e1])
#define KT_MEGA 64
__device__ __forceinline__ void mega_map(int kt, int rr, int e0, int e1,
                                         const __half*& Ap, int& sA, const __half*& Bp) {
    if (kt < 32) {
        Ap = g_H2 + (size_t)rr * 4096 * HS + (size_t)kt * BK;
        sA = HS;
        Bp = g_sw2h + (size_t)kt * BK * C_DIM;
    } else if (kt < 48) {
        Ap = g_Hr + (size_t)rr * 4096 * HR + (size_t)(kt - 32) * BK;
        sA = HR;
        Bp = g_w2h + (size_t)e0 * HR * C_DIM + (size_t)(kt - 32) * BK * C_DIM;
    } else {
        Ap = g_Hr + (size_t)(8 + rr) * 4096 * HR + (size_t)(kt - 48) * BK;
        sA = HR;
        Bp = g_w2h + (size_t)e1 * HR * C_DIM + (size_t)(kt - 48) * BK * C_DIM;
    }
}
__device__ __forceinline__ void fill_stage_mega(
    int kt, int rr, int e0, int e1, int m0, int n0,
    __half* Asb, __half* Bsb, int tid)
{
    const __half* Ap; const __half* Bp; int sA;
    mega_map(kt, rr, e0, e1, Ap, sA, Bp);
#pragma unroll
    for (int i = 0; i < 4; i++) {
        int c = tid + i * 256;
        int ar = c >> 3, ac = c & 7;
        cp16(Asb + ar * ASTR + ac * 8,
             Ap + (size_t)(m0 + ar) * sA + ac * 8);
    }
#pragma unroll
    for (int i = 0; i < 4; i++) {
        int c = tid + i * 256;
        int br = c >> 4, bc = c & 15;
        cp16(Bsb + br * BSTR + bc * 8,
             Bp + (size_t)br * C_DIM + n0 + bc * 8);
    }
}
__global__ __launch_bounds__(256, 2) void k_down_mega(float* __restrict__ dout)
{
    extern __shared__ __align__(16) __half smem[];
    __half* Asm = smem;
    __half* Bsm = smem + NSTG * A_ST;

    const int rr = blockIdx.z;
    const int e0 = (3 * rr) & 7;
    const int e1 = (3 * rr + 7) & 7;
    const int tid = threadIdx.x;
    const int m0 = blockIdx.y * BM;
    const int n0 = blockIdx.x * BN;

    unsigned linbid = blockIdx.x + 8u * (blockIdx.y + 32u * blockIdx.z);
    stagger(linbid);

#pragma unroll
    for (int c = 0; c < NSTG - 1; c++) {
        fill_stage_mega(c, rr, e0, e1, m0, n0,
                        Asm + c * A_ST, Bsm + c * B_ST, tid);
        asm volatile("cp.async.commit_group;");
    }

    float acc[2][8][4];
#pragma unroll
    for (int i = 0; i < 2; i++)
#pragma unroll
        for (int j = 0; j < 8; j++)
#pragma unroll
            for (int e = 0; e < 4; e++) acc[i][j][e] = 0.f;

    const int warp = tid >> 5, lane = tid & 31;
    const int wm = warp & 3, wn = warp >> 2;

    int s = 0, fs = NSTG - 1;
    for (int kt = 0; kt < KT_MEGA; ++kt) {
        asm volatile("cp.async.wait_group %0;" :: "n"(NSTG - 2));
        __syncthreads();

        compute_stage(Asm + s * A_ST, Bsm + s * B_ST, acc, wm, wn, lane);

        if (kt + NSTG - 1 < KT_MEGA)
            fill_stage_mega(kt + NSTG - 1, rr, e0, e1, m0, n0,
                            Asm + fs * A_ST, Bsm + fs * B_ST, tid);
        asm volatile("cp.async.commit_group;");

        if (++s == NSTG) s = 0;
        if (++fs == NSTG) fs = 0;
    }

    // epilogue: single fp32 write, precomputed combined bias, un-permute rows
    const float* biasD = g_biasD + rr * C_DIM;
#pragma unroll
    for (int mi = 0; mi < 2; mi++)
#pragma unroll
        for (int ni = 0; ni < 8; ni++)
#pragma unroll
            for (int pp = 0; pp < 2; pp++) {
                int rowl = m0 + wm * 32 + mi * 16 + (lane >> 2) + pp * 8;
                int col  = n0 + wn * 64 + ni * 8 + (lane & 3) * 2;
                float2 bb = *(const float2*)(biasD + col);
                float2 f;
                f.x = acc[mi][ni][2 * pp + 0] + bb.x;
                f.y = acc[mi][ni][2 * pp + 1] + bb.y;
                size_t t = (size_t)rr + 8 * (size_t)rowl;    // actual token
                *(float2*)(dout + t * C_DIM + col) = f;
            }
}

// ---------------- launch ----------------
extern "C" void kernel_launch(void* const* d_in, const int* in_sizes, int n_in,
                              void* d_out, int out_size) {
    const float* x   = (const float*)d_in[0];
    // d_in[1] = t_emb : unused by reference
    const float* sw1 = (const float*)d_in[2];
    const float* sb1 = (const float*)d_in[3];
    const float* sw3 = (const float*)d_in[4];
    const float* sb3 = (const float*)d_in[5];
    const float* sw2 = (const float*)d_in[6];
    const float* sb2 = (const float*)d_in[7];
    const float* w1  = (const float*)d_in[8];
    const float* b1  = (const float*)d_in[9];
    const float* w2  = (const float*)d_in[10];
    const float* b2  = (const float*)d_in[11];
    float* out = (float*)d_out;

    cudaFuncSetAttribute(k_up_all,    cudaFuncAttributeMaxDynamicSharedMemorySize, SMEM_BYTES);
    cudaFuncSetAttribute(k_down_mega, cudaFuncAttributeMaxDynamicSharedMemorySize, SMEM_BYTES);

    // one merged conversion launch (MLP x4) + tiny bias kernel
    k_convall<<<CV_QUARTER / 256, 256>>>(x, sw1, sw3, sw2, w1, w2);
    k_bias<<<(NE * C_DIM + 255) / 256, 256>>>(sb2, b2);

    // merged up path: shared SwiGLU (8192 CTAs) + routed gelu (4096 CTAs)
    k_up_all<<<12288, 256, SMEM_BYTES>>>(sb1, sb3, b1);

    // fused down path: single pass, single out write
    k_down_mega<<<dim3(C_DIM / BN, 4096 / BM, 8), 256, SMEM_BYTES>>>(out);
}